// round 15
// baseline (speedup 1.0000x reference)
#include <cuda_runtime.h>

// UniSURF renderer, piecewise-linear prefix march + bracket-local secant,
// balanced single-wave scheduling.
//
// z(d) = b2 + sum_j W_j relu(A_j + d R_j) = K0 + K1 d + sum_j U_j |d - t_j|
// March: bucket breakpoints (no sort), running alpha/beta prefix -> ~4 FMA
// per sample; capture (aL,bL,zl,zh,idx) at the first crossing. Secant: z in
// the bracket = aL + bL*dm + corrections from ONLY the units bucketed into
// segment idx+1 (captured once). Grid: 1024x64, warp-granular chunks of 32
// rays, exactly 2 chunks per warp -> one balanced wave, no straggler tail.

#define HID     32
#define NPAIR   16
#define NSTEPS  32
#define NSECANT 8
#define NEARV   0.5f
#define EPSV    1e-6f
#define RTINY   1e-30f
#define THREADS 64
#define NBLK    1024
#define NCAP    8

typedef unsigned long long ull;
typedef unsigned int uint32;

__device__ __forceinline__ ull pack2(float x, float y) {
    ull r;
    asm("mov.b64 %0, {%1, %2};" : "=l"(r) : "f"(x), "f"(y));
    return r;
}

__device__ __forceinline__ void unpack2(ull v, float& x, float& y) {
    asm("mov.b64 {%0, %1}, %2;" : "=f"(x), "=f"(y) : "l"(v));
}

__device__ __forceinline__ float sigmoidf_(float z) {
    return 1.0f / (1.0f + __expf(-z));
}

// bracket-local eval: prefix line + captured breakpoint corrections
__device__ __forceinline__ float zeval_bracket(float dm, float aL, float bL,
                                               int cnt, uint32 negmask,
                                               const ull* col) {
    float z = fmaf(bL, dm, aL);
#pragma unroll 1
    for (int q = 0; q < cnt; q++) {
        float Pv, Qv;
        unpack2(col[q * THREADS], Pv, Qv);
        const float e = fmaf(Qv, dm, Pv);
        z += ((negmask >> q) & 1u) ? fminf(e, 0.0f) : fmaxf(e, 0.0f);
    }
    return z;
}

// full MLP eval (overflow fallback; rare)
__device__ __forceinline__ float zfull(float dm, float rx, float ry, float rz,
                                       const float* w1x, const float* w1y,
                                       const float* w1z, const float* sA,
                                       const float* sV, float b2v) {
    float z = b2v;
#pragma unroll
    for (int j = 0; j < HID; j++) {
        const float r = fmaf(rx, w1x[j], fmaf(ry, w1y[j], rz * w1z[j]));
        const float pre = fmaf(dm, r, sA[j]);
        z = fmaf(2.0f * sV[j], fmaxf(pre, 0.0f), z);
    }
    return z;
}

__global__ void __launch_bounds__(THREADS, 11) unisurf_kernel(
    const float* __restrict__ cam, const float* __restrict__ dirs,
    const float* __restrict__ W1, const float* __restrict__ b1,
    const float* __restrict__ W2, const float* __restrict__ b2,
    float* __restrict__ out, int P)
{
    __shared__ float sW1[3][HID];
    __shared__ float sA[HID];                 // A_j
    __shared__ float sV[HID];                 // 0.5 * W2_j
    __shared__ float sVA[HID];                // 0.5 * W2_j * |A_j|
    __shared__ float sMisc[6];                // cam0..2, b2, |cam|^2, K0
    __shared__ ull   bPQ[NSTEPS][THREADS];    // buckets; rows 0..7 reused
                                              // post-march for captures

    const int tid = threadIdx.x;
    if (tid < HID) {
        const float c0 = cam[0], c1 = cam[1], c2 = cam[2];
        const float w0 = W1[tid], w1 = W1[HID + tid], w2 = W1[2 * HID + tid];
        sW1[0][tid] = w0;
        sW1[1][tid] = w1;
        sW1[2][tid] = w2;
        const float Aj = fmaf(c0, w0, fmaf(c1, w1, fmaf(c2, w2, b1[tid])));
        const float Wj = W2[tid];
        sA[tid] = Aj;
        sV[tid] = 0.5f * Wj;
        sVA[tid] = 0.5f * Wj * fabsf(Aj);
        if (tid == 0) {
            sMisc[0] = c0; sMisc[1] = c1; sMisc[2] = c2;
            sMisc[3] = b2[0];
            sMisc[4] = c0 * c0 + c1 * c1 + c2 * c2;
        }
    }
    __syncthreads();
    if (tid == 0) {   // K0 = b2 + sum_j 0.5 W_j A_j
        float k0 = sMisc[3];
        for (int j = 0; j < HID; j++) k0 = fmaf(sV[j], sA[j], k0);
        sMisc[5] = k0;
    }
    __syncthreads();

    const float c0 = sMisc[0], c1 = sMisc[1], c2 = sMisc[2];
    const float b2v = sMisc[3], cc = sMisc[4], K0 = sMisc[5];
    const float stepc = 1.0f / (float)(NSTEPS - 1);

    // warp-granular chunks of 32 rays; 2048 warps x exactly 2 chunks.
    const int lane = tid & 31;
    const int gw = blockIdx.x * (THREADS / 32) + (tid >> 5);
    const int totalw = gridDim.x * (THREADS / 32);
    const int nchunks = (P + 31) >> 5;

    for (int c = gw; c < nchunks; c += totalw) {
        const int p = (c << 5) + lane;
        const int pc = p < P ? p : (P - 1);

        const float dx = dirs[3 * pc + 0];
        const float dy = dirs[3 * pc + 1];
        const float dz = dirs[3 * pc + 2];
        const float invn = rsqrtf(dx * dx + dy * dy + dz * dz);
        const float rx = dx * invn, ry = dy * invn, rz = dz * invn;

        const float rcd = rx * c0 + ry * c1 + rz * c2;
        const float under = rcd * rcd - (cc - 1.0f);   // radius = 1
        const bool hit = under > 0.0f;
        const float s = sqrtf(fmaxf(under, 0.0f));
        const float far = fmaxf(s - rcd, NEARV + EPSV);
        const float stepd = (far - NEARV) * stepc;
        const float invstep = __fdividef(1.0f, stepd);
        const float nfbias = -NEARV * invstep;

        // zero buckets (per-thread column)
#pragma unroll
        for (int k = 1; k < NSTEPS; k++) bPQ[k][tid] = 0ull;

        // per-unit setup: breakpoint bucketing, alpha/beta init
        float alpha = K0;
        float beta = 0.0f;
#pragma unroll 1
        for (int k2 = 0; k2 < NPAIR; k2++) {
            const int j = 2 * k2;
            float rr[2];
            rr[0] = fmaf(rx, sW1[0][j], fmaf(ry, sW1[1][j], rz * sW1[2][j]));
            rr[1] = fmaf(rx, sW1[0][j + 1],
                    fmaf(ry, sW1[1][j + 1], rz * sW1[2][j + 1]));
#pragma unroll
            for (int h = 0; h < 2; h++) {
                const int jj = j + h;
                const float rj = rr[h];
                const float aj = sA[jj];
                const bool tiny = fabsf(rj) < RTINY;
                float t = __fdividef(-aj, rj);
                t = tiny ? 0.0f : t;
                const float U = sV[jj] * fabsf(rj);
                const float Ut = U * t;
                const float nf = fmaf(t, invstep, nfbias);
                beta += (rj < 0.0f) ? (-2.0f * U) : 0.0f;
                alpha += Ut;
                alpha += tiny ? sVA[jj] : 0.0f;
                if (nf <= 0.0f) {           // breakpoint at/below near
                    beta = fmaf(2.0f, U, beta);
                    alpha = fmaf(-2.0f, Ut, alpha);
                } else if (nf <= 31.0f) {   // breakpoint inside march range
                    const int kb = __float2int_ru(nf);  // 1..31
                    float bp, bq;
                    unpack2(bPQ[kb][tid], bp, bq);
                    bPQ[kb][tid] = pack2(bp + U, bq + Ut);
                }
            }
        }

        // march with register capture of the crossing bracket state
        float d = NEARV;
        float zprev = fmaf(beta, d, alpha);
        int idx = 0;
        bool found = false;
        float aL = 0.0f, bL = 0.0f, zl = 0.0f, zh = 0.0f;
        ull pf1 = bPQ[1][tid];
        ull pf2 = bPQ[2][tid];
#pragma unroll 1
        for (int k = 1; k <= NSTEPS - 3; k++) {   // k = 1..29
            const ull cur = pf1;
            pf1 = pf2;
            pf2 = bPQ[k + 2][tid];
            float bp, bq;
            unpack2(cur, bp, bq);
            const float aprev = alpha, bprev = beta;
            beta = fmaf(2.0f, bp, beta);
            alpha = fmaf(-2.0f, bq, alpha);
            d += stepd;
            const float z = fmaf(beta, d, alpha);
            const bool cross = (zprev < 0.0f) && (z >= 0.0f);
            const bool take = cross && !found;
            idx = take ? (k - 1) : idx;
            aL = take ? aprev : aL;
            bL = take ? bprev : bL;
            zl = take ? zprev : zl;
            zh = take ? z : zh;
            found |= cross;
            zprev = z;
        }
#pragma unroll
        for (int k = NSTEPS - 2; k <= NSTEPS - 1; k++) {  // k = 30, 31
            const ull cur = (k == NSTEPS - 2) ? pf1 : pf2;
            float bp, bq;
            unpack2(cur, bp, bq);
            const float aprev = alpha, bprev = beta;
            beta = fmaf(2.0f, bp, beta);
            alpha = fmaf(-2.0f, bq, alpha);
            d += stepd;
            const float z = fmaf(beta, d, alpha);
            const bool cross = (zprev < 0.0f) && (z >= 0.0f);
            const bool take = cross && !found;
            idx = take ? (k - 1) : idx;
            aL = take ? aprev : aL;
            bL = take ? bprev : bL;
            zl = take ? zprev : zl;
            zh = take ? z : zh;
            found |= cross;
            zprev = z;
        }

        float dpred = 0.0f, osurf = 0.0f;
        const bool ok = found && hit;

        if (ok) {
            // capture pass: replay the EXACT setup bucketing computation and
            // collect units whose breakpoint lands in bucket idx+1.
            int cnt = 0;
            uint32 negmask = 0u;
            bool ovf = false;
            const int kbwant = idx + 1;
#pragma unroll 1
            for (int k2 = 0; k2 < NPAIR; k2++) {
                const int j = 2 * k2;
                float rr[2];
                rr[0] = fmaf(rx, sW1[0][j],
                        fmaf(ry, sW1[1][j], rz * sW1[2][j]));
                rr[1] = fmaf(rx, sW1[0][j + 1],
                        fmaf(ry, sW1[1][j + 1], rz * sW1[2][j + 1]));
#pragma unroll
                for (int h = 0; h < 2; h++) {
                    const int jj = j + h;
                    const float rj = rr[h];
                    const float aj = sA[jj];
                    const bool tiny = fabsf(rj) < RTINY;
                    float t = __fdividef(-aj, rj);
                    t = tiny ? 0.0f : t;
                    const float nf = fmaf(t, invstep, nfbias);
                    if (!(nf <= 0.0f) && (nf <= 31.0f) &&
                        (__float2int_ru(nf) == kbwant)) {
                        if (cnt < NCAP) {
                            const float w = 2.0f * sV[jj];
                            const float sgn = (rj < 0.0f) ? -1.0f : 1.0f;
                            bPQ[cnt][tid] = pack2(w * sgn * aj, w * sgn * rj);
                            negmask |= (w < 0.0f ? 1u : 0u) << cnt;
                            cnt++;
                        } else {
                            ovf = true;
                        }
                    }
                }
            }

            const ull* col = &bPQ[0][tid];
            const float tl = (float)idx * stepc;
            const float th = (float)(idx + 1) * stepc;
            float dl = fmaf(far, tl, NEARV * (1.0f - tl));
            float dh = fmaf(far, th, NEARV * (1.0f - th));
            float fl = sigmoidf_(zl) - 0.5f;
            float fh = sigmoidf_(zh) - 0.5f;

#pragma unroll 1
            for (int it = 0; it < NSECANT; it++) {
                float den = fh - fl;
                if (fabsf(den) < EPSV) den = EPSV;
                const float dm = dl - __fdividef(fl * (dh - dl), den);
                float zm;
                if (ovf) {
                    zm = zfull(dm, rx, ry, rz, sW1[0], sW1[1], sW1[2],
                               sA, sV, b2v);
                } else {
                    zm = zeval_bracket(dm, aL, bL, cnt, negmask, col);
                }
                const float fm = sigmoidf_(zm) - 0.5f;
                if (fm < 0.0f) { dl = dm; fl = fm; }
                else           { dh = dm; fh = fm; }
            }
            float den = fh - fl;
            if (fabsf(den) < EPSV) den = EPSV;
            dpred = dl - __fdividef(fl * (dh - dl), den);
            float zs;
            if (ovf) {
                zs = zfull(dpred, rx, ry, rz, sW1[0], sW1[1], sW1[2],
                           sA, sV, b2v);
            } else {
                zs = zeval_bracket(dpred, aL, bL, cnt, negmask, col);
            }
            osurf = sigmoidf_(zs);
        }

        if (p < P) {
            out[p] = dpred;
            out[P + p] = osurf;
        }
    }
}

extern "C" void kernel_launch(void* const* d_in, const int* in_sizes, int n_in,
                              void* d_out, int out_size)
{
    const float* cam  = (const float*)d_in[0];
    const float* dirs = (const float*)d_in[1];
    const float* W1   = (const float*)d_in[2];
    const float* b1   = (const float*)d_in[3];
    const float* W2   = (const float*)d_in[4];
    const float* b2   = (const float*)d_in[5];
    float* out = (float*)d_out;

    const int P = in_sizes[1] / 3;
    const int nchunks = (P + 31) >> 5;
    int blocks = NBLK;
    const int maxb = (nchunks + 1) / 2;   // 2 warps per block
    if (blocks > maxb) blocks = maxb;
    if (blocks < 1) blocks = 1;
    unisurf_kernel<<<blocks, THREADS>>>(cam, dirs, W1, b1, W2, b2, out, P);
}

// round 16
// speedup vs baseline: 1.4288x; 1.4288x over previous
#include <cuda_runtime.h>

// UniSURF renderer, piecewise-linear prefix march + bracket-local secant.
// R14 base (best verified), flat grid: 1 ray/thread, 2048x64.
//
// z(d) = b2 + sum_j W_j relu(A_j + d R_j) = K0 + K1 d + sum_j U_j |d - t_j|
// March: bucket breakpoints (no sort), running alpha/beta prefix -> ~4 FMA
// per sample; capture (aL,bL,idx) at the first crossing (zl/zh reconstructed
// from the captured line + corrections -> fewer march selects). Secant: z in
// the bracket = aL + bL*dm + corrections from ONLY the units bucketed into
// segment idx+1 (captured once; avg ~1 unit).

#define HID     32
#define NPAIR   16
#define NSTEPS  32
#define NSECANT 8
#define NEARV   0.5f
#define EPSV    1e-6f
#define RTINY   1e-30f
#define THREADS 64
#define NCAP    8

typedef unsigned long long ull;
typedef unsigned int uint32;

__device__ __forceinline__ ull pack2(float x, float y) {
    ull r;
    asm("mov.b64 %0, {%1, %2};" : "=l"(r) : "f"(x), "f"(y));
    return r;
}

__device__ __forceinline__ void unpack2(ull v, float& x, float& y) {
    asm("mov.b64 {%0, %1}, %2;" : "=f"(x), "=f"(y) : "l"(v));
}

__device__ __forceinline__ float sigmoidf_(float z) {
    return 1.0f / (1.0f + __expf(-z));
}

// bracket-local eval: prefix line + captured breakpoint corrections
__device__ __forceinline__ float zeval_bracket(float dm, float aL, float bL,
                                               int cnt, uint32 negmask,
                                               const ull* col) {
    float z = fmaf(bL, dm, aL);
#pragma unroll 1
    for (int q = 0; q < cnt; q++) {
        float Pv, Qv;
        unpack2(col[q * THREADS], Pv, Qv);
        const float e = fmaf(Qv, dm, Pv);
        z += ((negmask >> q) & 1u) ? fminf(e, 0.0f) : fmaxf(e, 0.0f);
    }
    return z;
}

// full MLP eval (overflow fallback; rare)
__device__ __forceinline__ float zfull(float dm, float rx, float ry, float rz,
                                       const float* w1x, const float* w1y,
                                       const float* w1z, const float* sA,
                                       const float* sV, float b2v) {
    float z = b2v;
#pragma unroll
    for (int j = 0; j < HID; j++) {
        const float r = fmaf(rx, w1x[j], fmaf(ry, w1y[j], rz * w1z[j]));
        const float pre = fmaf(dm, r, sA[j]);
        z = fmaf(2.0f * sV[j], fmaxf(pre, 0.0f), z);
    }
    return z;
}

__global__ void __launch_bounds__(THREADS, 12) unisurf_kernel(
    const float* __restrict__ cam, const float* __restrict__ dirs,
    const float* __restrict__ W1, const float* __restrict__ b1,
    const float* __restrict__ W2, const float* __restrict__ b2,
    float* __restrict__ out, int P)
{
    __shared__ float sW1[3][HID];
    __shared__ float sA[HID];                 // A_j
    __shared__ float sV[HID];                 // 0.5 * W2_j
    __shared__ float sVA[HID];                // 0.5 * W2_j * |A_j|
    __shared__ float sMisc[6];                // cam0..2, b2, |cam|^2, K0
    __shared__ ull   bPQ[NSTEPS][THREADS];    // buckets; rows 0..7 reused
                                              // post-march for captures

    const int tid = threadIdx.x;
    if (tid < HID) {
        const float c0 = cam[0], c1 = cam[1], c2 = cam[2];
        const float w0 = W1[tid], w1 = W1[HID + tid], w2 = W1[2 * HID + tid];
        sW1[0][tid] = w0;
        sW1[1][tid] = w1;
        sW1[2][tid] = w2;
        const float Aj = fmaf(c0, w0, fmaf(c1, w1, fmaf(c2, w2, b1[tid])));
        const float Wj = W2[tid];
        sA[tid] = Aj;
        sV[tid] = 0.5f * Wj;
        sVA[tid] = 0.5f * Wj * fabsf(Aj);
        if (tid == 0) {
            sMisc[0] = c0; sMisc[1] = c1; sMisc[2] = c2;
            sMisc[3] = b2[0];
            sMisc[4] = c0 * c0 + c1 * c1 + c2 * c2;
        }
    }
    __syncthreads();
    if (tid == 0) {   // K0 = b2 + sum_j 0.5 W_j A_j
        float k0 = sMisc[3];
        for (int j = 0; j < HID; j++) k0 = fmaf(sV[j], sA[j], k0);
        sMisc[5] = k0;
    }
    __syncthreads();

    const int p = blockIdx.x * THREADS + tid;
    if (p >= P) return;

    const float c0 = sMisc[0], c1 = sMisc[1], c2 = sMisc[2];
    const float b2v = sMisc[3], cc = sMisc[4], K0 = sMisc[5];
    const float stepc = 1.0f / (float)(NSTEPS - 1);

    const float dx = dirs[3 * p + 0];
    const float dy = dirs[3 * p + 1];
    const float dz = dirs[3 * p + 2];
    const float invn = rsqrtf(dx * dx + dy * dy + dz * dz);
    const float rx = dx * invn, ry = dy * invn, rz = dz * invn;

    const float rcd = rx * c0 + ry * c1 + rz * c2;
    const float under = rcd * rcd - (cc - 1.0f);   // radius = 1
    const bool hit = under > 0.0f;
    const float s = sqrtf(fmaxf(under, 0.0f));
    const float far = fmaxf(s - rcd, NEARV + EPSV);
    const float stepd = (far - NEARV) * stepc;
    const float invstep = __fdividef(1.0f, stepd);
    const float nfbias = -NEARV * invstep;

    // zero buckets (per-thread column)
#pragma unroll
    for (int k = 1; k < NSTEPS; k++) bPQ[k][tid] = 0ull;

    // per-unit setup: breakpoint bucketing, alpha/beta init
    float alpha = K0;
    float beta = 0.0f;
#pragma unroll 4
    for (int k2 = 0; k2 < NPAIR; k2++) {
        const int j = 2 * k2;
        float rr[2];
        rr[0] = fmaf(rx, sW1[0][j], fmaf(ry, sW1[1][j], rz * sW1[2][j]));
        rr[1] = fmaf(rx, sW1[0][j + 1],
                fmaf(ry, sW1[1][j + 1], rz * sW1[2][j + 1]));
#pragma unroll
        for (int h = 0; h < 2; h++) {
            const int jj = j + h;
            const float rj = rr[h];
            const float aj = sA[jj];
            const bool tiny = fabsf(rj) < RTINY;
            float t = __fdividef(-aj, rj);
            t = tiny ? 0.0f : t;
            const float U = sV[jj] * fabsf(rj);
            const float Ut = U * t;
            const float nf = fmaf(t, invstep, nfbias);
            beta += (rj < 0.0f) ? (-2.0f * U) : 0.0f;
            alpha += Ut;
            alpha += tiny ? sVA[jj] : 0.0f;
            if (nf <= 0.0f) {           // breakpoint at/below near
                beta = fmaf(2.0f, U, beta);
                alpha = fmaf(-2.0f, Ut, alpha);
            } else if (nf <= 31.0f) {   // breakpoint inside march range
                const int kb = __float2int_ru(nf);  // 1..31
                float bp, bq;
                unpack2(bPQ[kb][tid], bp, bq);
                bPQ[kb][tid] = pack2(bp + U, bq + Ut);
            }
        }
    }

    // march with register capture of the crossing line (aL,bL,idx only)
    float d = NEARV;
    float zprev = fmaf(beta, d, alpha);
    int idx = 0;
    bool found = false;
    float aL = 0.0f, bL = 0.0f;
    ull pf1 = bPQ[1][tid];
    ull pf2 = bPQ[2][tid];
#pragma unroll 1
    for (int k = 1; k <= NSTEPS - 3; k++) {   // k = 1..29
        const ull cur = pf1;
        pf1 = pf2;
        pf2 = bPQ[k + 2][tid];
        float bp, bq;
        unpack2(cur, bp, bq);
        const float aprev = alpha, bprev = beta;
        beta = fmaf(2.0f, bp, beta);
        alpha = fmaf(-2.0f, bq, alpha);
        d += stepd;
        const float z = fmaf(beta, d, alpha);
        const bool cross = (zprev < 0.0f) && (z >= 0.0f);
        const bool take = cross && !found;
        idx = take ? (k - 1) : idx;
        aL = take ? aprev : aL;
        bL = take ? bprev : bL;
        found |= cross;
        zprev = z;
    }
#pragma unroll
    for (int k = NSTEPS - 2; k <= NSTEPS - 1; k++) {  // k = 30, 31
        const ull cur = (k == NSTEPS - 2) ? pf1 : pf2;
        float bp, bq;
        unpack2(cur, bp, bq);
        const float aprev = alpha, bprev = beta;
        beta = fmaf(2.0f, bp, beta);
        alpha = fmaf(-2.0f, bq, alpha);
        d += stepd;
        const float z = fmaf(beta, d, alpha);
        const bool cross = (zprev < 0.0f) && (z >= 0.0f);
        const bool take = cross && !found;
        idx = take ? (k - 1) : idx;
        aL = take ? aprev : aL;
        bL = take ? bprev : bL;
        found |= cross;
        zprev = z;
    }

    float dpred = 0.0f, osurf = 0.0f;
    const bool ok = found && hit;

    if (ok) {
        // capture pass: replay the EXACT setup bucketing computation and
        // collect units whose breakpoint lands in bucket idx+1.
        int cnt = 0;
        uint32 negmask = 0u;
        bool ovf = false;
        const int kbwant = idx + 1;
#pragma unroll 4
        for (int k2 = 0; k2 < NPAIR; k2++) {
            const int j = 2 * k2;
            float rr[2];
            rr[0] = fmaf(rx, sW1[0][j], fmaf(ry, sW1[1][j], rz * sW1[2][j]));
            rr[1] = fmaf(rx, sW1[0][j + 1],
                    fmaf(ry, sW1[1][j + 1], rz * sW1[2][j + 1]));
#pragma unroll
            for (int h = 0; h < 2; h++) {
                const int jj = j + h;
                const float rj = rr[h];
                const float aj = sA[jj];
                const bool tiny = fabsf(rj) < RTINY;
                float t = __fdividef(-aj, rj);
                t = tiny ? 0.0f : t;
                const float nf = fmaf(t, invstep, nfbias);
                if (!(nf <= 0.0f) && (nf <= 31.0f) &&
                    (__float2int_ru(nf) == kbwant)) {
                    if (cnt < NCAP) {
                        const float w = 2.0f * sV[jj];
                        const float sgn = (rj < 0.0f) ? -1.0f : 1.0f;
                        bPQ[cnt][tid] = pack2(w * sgn * aj, w * sgn * rj);
                        negmask |= (w < 0.0f ? 1u : 0u) << cnt;
                        cnt++;
                    } else {
                        ovf = true;
                    }
                }
            }
        }

        const ull* col = &bPQ[0][tid];
        const float tl = (float)idx * stepc;
        const float th = (float)(idx + 1) * stepc;
        float dl = fmaf(far, tl, NEARV * (1.0f - tl));
        float dh = fmaf(far, th, NEARV * (1.0f - th));
        // bracket z values reconstructed (corrections vanish at dl)
        float zl, zh;
        if (ovf) {
            zl = zfull(dl, rx, ry, rz, sW1[0], sW1[1], sW1[2], sA, sV, b2v);
            zh = zfull(dh, rx, ry, rz, sW1[0], sW1[1], sW1[2], sA, sV, b2v);
        } else {
            zl = fmaf(bL, dl, aL);
            zh = zeval_bracket(dh, aL, bL, cnt, negmask, col);
        }
        float fl = sigmoidf_(zl) - 0.5f;
        float fh = sigmoidf_(zh) - 0.5f;

#pragma unroll 1
        for (int it = 0; it < NSECANT; it++) {
            float den = fh - fl;
            if (fabsf(den) < EPSV) den = EPSV;
            const float dm = dl - __fdividef(fl * (dh - dl), den);
            float zm;
            if (ovf) {
                zm = zfull(dm, rx, ry, rz, sW1[0], sW1[1], sW1[2],
                           sA, sV, b2v);
            } else {
                zm = zeval_bracket(dm, aL, bL, cnt, negmask, col);
            }
            const float fm = sigmoidf_(zm) - 0.5f;
            if (fm < 0.0f) { dl = dm; fl = fm; }
            else           { dh = dm; fh = fm; }
        }
        float den = fh - fl;
        if (fabsf(den) < EPSV) den = EPSV;
        dpred = dl - __fdividef(fl * (dh - dl), den);
        float zs;
        if (ovf) {
            zs = zfull(dpred, rx, ry, rz, sW1[0], sW1[1], sW1[2],
                       sA, sV, b2v);
        } else {
            zs = zeval_bracket(dpred, aL, bL, cnt, negmask, col);
        }
        osurf = sigmoidf_(zs);
    }

    out[p] = dpred;
    out[P + p] = osurf;
}

extern "C" void kernel_launch(void* const* d_in, const int* in_sizes, int n_in,
                              void* d_out, int out_size)
{
    const float* cam  = (const float*)d_in[0];
    const float* dirs = (const float*)d_in[1];
    const float* W1   = (const float*)d_in[2];
    const float* b1   = (const float*)d_in[3];
    const float* W2   = (const float*)d_in[4];
    const float* b2   = (const float*)d_in[5];
    float* out = (float*)d_out;

    const int P = in_sizes[1] / 3;
    int blocks = (P + THREADS - 1) / THREADS;
    if (blocks < 1) blocks = 1;
    unisurf_kernel<<<blocks, THREADS>>>(cam, dirs, W1, b1, W2, b2, out, P);
}

// round 17
// speedup vs baseline: 1.5308x; 1.0714x over previous
#include <cuda_runtime.h>

// UniSURF renderer, piecewise-linear prefix march + bracket-local secant.
// Flat grid (1 ray/thread, 2048x64), R16 base plus:
//  - packed bucket-index registers (5b x 12 per ull): capture pass reads the
//    stored kb instead of replaying the div/ceil chain (bit-exact consistent)
//  - cooperative STS.128 bucket zeroing + one __syncthreads
//  - fully unrolled setup/capture (compile-time unit indices)

#define HID     32
#define NPAIR   16
#define NSTEPS  32
#define NSECANT 8
#define NEARV   0.5f
#define EPSV    1e-6f
#define RTINY   1e-30f
#define THREADS 64
#define NCAP    8

typedef unsigned long long ull;
typedef unsigned int uint32;

__device__ __forceinline__ ull pack2(float x, float y) {
    ull r;
    asm("mov.b64 %0, {%1, %2};" : "=l"(r) : "f"(x), "f"(y));
    return r;
}

__device__ __forceinline__ void unpack2(ull v, float& x, float& y) {
    asm("mov.b64 {%0, %1}, %2;" : "=f"(x), "=f"(y) : "l"(v));
}

__device__ __forceinline__ float sigmoidf_(float z) {
    return 1.0f / (1.0f + __expf(-z));
}

// bracket-local eval: prefix line + captured breakpoint corrections
__device__ __forceinline__ float zeval_bracket(float dm, float aL, float bL,
                                               int cnt, uint32 negmask,
                                               const ull* col) {
    float z = fmaf(bL, dm, aL);
#pragma unroll 1
    for (int q = 0; q < cnt; q++) {
        float Pv, Qv;
        unpack2(col[q * THREADS], Pv, Qv);
        const float e = fmaf(Qv, dm, Pv);
        z += ((negmask >> q) & 1u) ? fminf(e, 0.0f) : fmaxf(e, 0.0f);
    }
    return z;
}

// full MLP eval (overflow fallback; rare)
__device__ __forceinline__ float zfull(float dm, float rx, float ry, float rz,
                                       const float* w1x, const float* w1y,
                                       const float* w1z, const float* sA,
                                       const float* sV, float b2v) {
    float z = b2v;
#pragma unroll
    for (int j = 0; j < HID; j++) {
        const float r = fmaf(rx, w1x[j], fmaf(ry, w1y[j], rz * w1z[j]));
        const float pre = fmaf(dm, r, sA[j]);
        z = fmaf(2.0f * sV[j], fmaxf(pre, 0.0f), z);
    }
    return z;
}

// compile-time packed-kb helpers (jj is a compile-time constant at expansion)
#define PKOR(jj, kb) do { \
    if ((jj) < 12)      pk0 |= ((ull)(uint32)(kb)) << (5 * (jj)); \
    else if ((jj) < 24) pk1 |= ((ull)(uint32)(kb)) << (5 * ((jj) - 12)); \
    else                pk2 |= ((ull)(uint32)(kb)) << (5 * ((jj) - 24)); \
} while (0)

#define PKGET(jj) \
    ((int)((((jj) < 12) ? (pk0 >> (5 * (jj))) \
          : ((jj) < 24) ? (pk1 >> (5 * ((jj) - 12))) \
          :               (pk2 >> (5 * ((jj) - 24)))) & 31ull))

__global__ void __launch_bounds__(THREADS, 12) unisurf_kernel(
    const float* __restrict__ cam, const float* __restrict__ dirs,
    const float* __restrict__ W1, const float* __restrict__ b1,
    const float* __restrict__ W2, const float* __restrict__ b2,
    float* __restrict__ out, int P)
{
    __shared__ float sW1[3][HID];
    __shared__ float sA[HID];                 // A_j
    __shared__ float sV[HID];                 // 0.5 * W2_j
    __shared__ float sVA[HID];                // 0.5 * W2_j * |A_j|
    __shared__ float sMisc[6];                // cam0..2, b2, |cam|^2, K0
    __shared__ __align__(16) ull bPQ[NSTEPS][THREADS];  // buckets; rows 0..7
                                              // reused post-march for captures

    const int tid = threadIdx.x;
    if (tid < HID) {
        const float c0 = cam[0], c1 = cam[1], c2 = cam[2];
        const float w0 = W1[tid], w1 = W1[HID + tid], w2 = W1[2 * HID + tid];
        sW1[0][tid] = w0;
        sW1[1][tid] = w1;
        sW1[2][tid] = w2;
        const float Aj = fmaf(c0, w0, fmaf(c1, w1, fmaf(c2, w2, b1[tid])));
        const float Wj = W2[tid];
        sA[tid] = Aj;
        sV[tid] = 0.5f * Wj;
        sVA[tid] = 0.5f * Wj * fabsf(Aj);
        if (tid == 0) {
            sMisc[0] = c0; sMisc[1] = c1; sMisc[2] = c2;
            sMisc[3] = b2[0];
            sMisc[4] = c0 * c0 + c1 * c1 + c2 * c2;
        }
    }
    __syncthreads();
    if (tid == 0) {   // K0 = b2 + sum_j 0.5 W_j A_j
        float k0 = sMisc[3];
        for (int j = 0; j < HID; j++) k0 = fmaf(sV[j], sA[j], k0);
        sMisc[5] = k0;
    }

    // cooperative vectorized zero of ALL bucket rows (uint4 = 2 ull each)
    {
        uint4* bz = reinterpret_cast<uint4*>(&bPQ[0][0]);
        const uint4 z4 = make_uint4(0u, 0u, 0u, 0u);
#pragma unroll
        for (int i = 0; i < (NSTEPS * THREADS / 2) / THREADS; i++)
            bz[tid + i * THREADS] = z4;
    }
    __syncthreads();

    const int p = blockIdx.x * THREADS + tid;
    const int pc = p < P ? p : (P - 1);

    const float c0 = sMisc[0], c1 = sMisc[1], c2 = sMisc[2];
    const float b2v = sMisc[3], cc = sMisc[4], K0 = sMisc[5];
    const float stepc = 1.0f / (float)(NSTEPS - 1);

    const float dx = dirs[3 * pc + 0];
    const float dy = dirs[3 * pc + 1];
    const float dz = dirs[3 * pc + 2];
    const float invn = rsqrtf(dx * dx + dy * dy + dz * dz);
    const float rx = dx * invn, ry = dy * invn, rz = dz * invn;

    const float rcd = rx * c0 + ry * c1 + rz * c2;
    const float under = rcd * rcd - (cc - 1.0f);   // radius = 1
    const bool hit = under > 0.0f;
    const float s = sqrtf(fmaxf(under, 0.0f));
    const float far = fmaxf(s - rcd, NEARV + EPSV);
    const float stepd = (far - NEARV) * stepc;
    const float invstep = __fdividef(1.0f, stepd);
    const float nfbias = -NEARV * invstep;

    // per-unit setup: breakpoint bucketing + packed-kb record
    float alpha = K0;
    float beta = 0.0f;
    ull pk0 = 0ull, pk1 = 0ull, pk2 = 0ull;

#define UNIT_SETUP(JJ, RJ) { \
    const float aj = sA[JJ]; \
    const bool tiny = fabsf(RJ) < RTINY; \
    float t = __fdividef(-aj, RJ); \
    t = tiny ? 0.0f : t; \
    const float U = sV[JJ] * fabsf(RJ); \
    const float Ut = U * t; \
    const float nf = fmaf(t, invstep, nfbias); \
    beta += ((RJ) < 0.0f) ? (-2.0f * U) : 0.0f; \
    alpha += Ut; \
    alpha += tiny ? sVA[JJ] : 0.0f; \
    if (nf <= 0.0f) { \
        beta = fmaf(2.0f, U, beta); \
        alpha = fmaf(-2.0f, Ut, alpha); \
    } else if (nf <= 31.0f) { \
        const int kb = __float2int_ru(nf); \
        float bp, bq; \
        unpack2(bPQ[kb][tid], bp, bq); \
        bPQ[kb][tid] = pack2(bp + U, bq + Ut); \
        PKOR(JJ, kb); \
    } }

#pragma unroll
    for (int k2 = 0; k2 < NPAIR; k2++) {
        const int j = 2 * k2;
        const float rr0 = fmaf(rx, sW1[0][j],
                          fmaf(ry, sW1[1][j], rz * sW1[2][j]));
        const float rr1 = fmaf(rx, sW1[0][j + 1],
                          fmaf(ry, sW1[1][j + 1], rz * sW1[2][j + 1]));
        UNIT_SETUP(j, rr0)
        UNIT_SETUP(j + 1, rr1)
    }
#undef UNIT_SETUP

    // march with register capture of the crossing line (aL,bL,idx)
    float d = NEARV;
    float zprev = fmaf(beta, d, alpha);
    int idx = 0;
    bool found = false;
    float aL = 0.0f, bL = 0.0f;
#pragma unroll 4
    for (int k = 1; k < NSTEPS; k++) {
        float bp, bq;
        unpack2(bPQ[k][tid], bp, bq);
        const float aprev = alpha, bprev = beta;
        beta = fmaf(2.0f, bp, beta);
        alpha = fmaf(-2.0f, bq, alpha);
        d += stepd;
        const float z = fmaf(beta, d, alpha);
        const bool cross = (zprev < 0.0f) && (z >= 0.0f);
        const bool take = cross && !found;
        idx = take ? (k - 1) : idx;
        aL = take ? aprev : aL;
        bL = take ? bprev : bL;
        found |= cross;
        zprev = z;
    }

    float dpred = 0.0f, osurf = 0.0f;
    const bool ok = found && hit;

    if (ok) {
        // capture pass: read stored bucket indices (bit-exact with scatter),
        // recompute r only for pairs containing a match.
        int cnt = 0;
        uint32 negmask = 0u;
        bool ovf = false;
        const int kbwant = idx + 1;

#define UNIT_CAPT(JJ, RJ) { \
    if (cnt < NCAP) { \
        const float w = 2.0f * sV[JJ]; \
        const float sgn = ((RJ) < 0.0f) ? -1.0f : 1.0f; \
        bPQ[cnt][tid] = pack2(w * sgn * sA[JJ], w * sgn * (RJ)); \
        negmask |= (w < 0.0f ? 1u : 0u) << cnt; \
        cnt++; \
    } else { \
        ovf = true; \
    } }

#pragma unroll
        for (int k2 = 0; k2 < NPAIR; k2++) {
            const int j = 2 * k2;
            const bool m0 = (PKGET(j) == kbwant);
            const bool m1 = (PKGET(j + 1) == kbwant);
            if (m0 || m1) {
                const float rr0 = fmaf(rx, sW1[0][j],
                                  fmaf(ry, sW1[1][j], rz * sW1[2][j]));
                const float rr1 = fmaf(rx, sW1[0][j + 1],
                                  fmaf(ry, sW1[1][j + 1], rz * sW1[2][j + 1]));
                if (m0) UNIT_CAPT(j, rr0)
                if (m1) UNIT_CAPT(j + 1, rr1)
            }
        }
#undef UNIT_CAPT

        const ull* col = &bPQ[0][tid];
        const float tl = (float)idx * stepc;
        const float th = (float)(idx + 1) * stepc;
        float dl = fmaf(far, tl, NEARV * (1.0f - tl));
        float dh = fmaf(far, th, NEARV * (1.0f - th));
        // bracket z values reconstructed (corrections vanish at dl)
        float zl, zh;
        if (ovf) {
            zl = zfull(dl, rx, ry, rz, sW1[0], sW1[1], sW1[2], sA, sV, b2v);
            zh = zfull(dh, rx, ry, rz, sW1[0], sW1[1], sW1[2], sA, sV, b2v);
        } else {
            zl = fmaf(bL, dl, aL);
            zh = zeval_bracket(dh, aL, bL, cnt, negmask, col);
        }
        float fl = sigmoidf_(zl) - 0.5f;
        float fh = sigmoidf_(zh) - 0.5f;

#pragma unroll 1
        for (int it = 0; it < NSECANT; it++) {
            float den = fh - fl;
            if (fabsf(den) < EPSV) den = EPSV;
            const float dm = dl - __fdividef(fl * (dh - dl), den);
            float zm;
            if (ovf) {
                zm = zfull(dm, rx, ry, rz, sW1[0], sW1[1], sW1[2],
                           sA, sV, b2v);
            } else {
                zm = zeval_bracket(dm, aL, bL, cnt, negmask, col);
            }
            const float fm = sigmoidf_(zm) - 0.5f;
            if (fm < 0.0f) { dl = dm; fl = fm; }
            else           { dh = dm; fh = fm; }
        }
        float den = fh - fl;
        if (fabsf(den) < EPSV) den = EPSV;
        dpred = dl - __fdividef(fl * (dh - dl), den);
        float zs;
        if (ovf) {
            zs = zfull(dpred, rx, ry, rz, sW1[0], sW1[1], sW1[2],
                       sA, sV, b2v);
        } else {
            zs = zeval_bracket(dpred, aL, bL, cnt, negmask, col);
        }
        osurf = sigmoidf_(zs);
    }

    if (p < P) {
        out[p] = dpred;
        out[P + p] = osurf;
    }
}

extern "C" void kernel_launch(void* const* d_in, const int* in_sizes, int n_in,
                              void* d_out, int out_size)
{
    const float* cam  = (const float*)d_in[0];
    const float* dirs = (const float*)d_in[1];
    const float* W1   = (const float*)d_in[2];
    const float* b1   = (const float*)d_in[3];
    const float* W2   = (const float*)d_in[4];
    const float* b2   = (const float*)d_in[5];
    float* out = (float*)d_out;

    const int P = in_sizes[1] / 3;
    int blocks = (P + THREADS - 1) / THREADS;
    if (blocks < 1) blocks = 1;
    unisurf_kernel<<<blocks, THREADS>>>(cam, dirs, W1, b1, W2, b2, out, P);
}